// round 11
// baseline (speedup 1.0000x reference)
#include <cuda_runtime.h>

#define HH 256
#define WW 256
#define NI 16
#define CC 3
#define HW (HH * WW)

__device__ __forceinline__ void stcs(float* p, float v) {
#if __CUDA_ARCH__ >= 800
    __stcs(p, v);
#else
    *p = v;
#endif
}

// grid: blockIdx.x = (b*256 + y)*2 + xtile ; block = 128 threads (half row)
__global__ __launch_bounds__(128, 14)
void warp_renderer_kernel(
    const float* __restrict__ g0,           // [B,NI,C,H,W]
    const float* __restrict__ m0,           // [B,NI,1,H,W]
    const float* __restrict__ mode_logits,  // [B,NI,5]
    const float* __restrict__ tp,           // [B,NI,6]
    const float* __restrict__ alpha,        // [B,NI,1]
    const float* __restrict__ inst_valid,   // [B,NI]
    const float* __restrict__ i_bg,         // [B,C,H,W]
    float* __restrict__ out,
    int B)
{
    __shared__ int   s_nact, s_ninact;
    __shared__ int   s_act_ni[NI];
    __shared__ float s_act_coef[NI];
    __shared__ float s_act_t0[NI], s_act_t3[NI];
    __shared__ float s_act_bx[NI], s_act_by[NI];
    __shared__ int   s_inact_ni[NI];

    const int b     = blockIdx.x >> 9;
    const int y     = (blockIdx.x >> 1) & 255;
    const int xtile = blockIdx.x & 1;

    // --- per-instance precompute + active compaction (lanes 0..15 of warp 0) ---
    if (threadIdx.x < NI) {
        const int lane = threadIdx.x;
        const int inst = b * NI + lane;
        const float* L = mode_logits + inst * 5;
        int mode = 0;
        float best = L[0];
        #pragma unroll
        for (int k = 1; k < 5; ++k) {
            float v = L[k];
            if (v > best) { best = v; mode = k; }  // first-max argmax
        }
        float coef;
        if (mode == 0 || mode == 2 || mode == 4) coef = 1.0f;       // static-like
        else if (mode == 3)                      coef = alpha[inst]; // blink
        else                                     coef = 0.0f;        // mode 1
        coef *= inst_valid[inst];

        const bool active = (coef != 0.0f);
        const unsigned mask = __ballot_sync(0x0000FFFFu, active);
        const unsigned lower = (1u << lane) - 1u;

        if (active) {
            const int pos = __popc(mask & lower);
            const float t0 = tp[inst * 6 + 0];
            const float t1 = tp[inst * 6 + 1];
            const float t2 = tp[inst * 6 + 2];
            const float t3 = tp[inst * 6 + 3];
            const float t4 = tp[inst * 6 + 4];
            const float t5 = tp[inst * 6 + 5];
            const float ys = (2.0f * (float)y + 1.0f) * (1.0f / (float)HH) - 1.0f;
            // ix = t0*x + bx ; iy = t3*x + by   (full chain folded)
            const float bx = 128.0f * (t1 * ys + t2) + 127.5f + 0.5f * t0 - 128.0f * t0;
            const float by = 128.0f * (t4 * ys + t5) + 127.5f + 0.5f * t3 - 128.0f * t3;
            s_act_ni[pos]   = lane;
            s_act_coef[pos] = coef;
            s_act_t0[pos]   = t0;
            s_act_t3[pos]   = t3;
            s_act_bx[pos]   = bx;
            s_act_by[pos]   = by;
        } else {
            const int pos = __popc((~mask) & 0xFFFFu & lower);
            s_inact_ni[pos] = lane;
        }
        if (lane == 0) {
            s_nact   = __popc(mask);
            s_ninact = NI - __popc(mask);
        }
    }
    __syncthreads();

    const int x   = xtile * 128 + threadIdx.x;
    const int pix = y * WW + x;
    const float xf = (float)x;

    const int n_gpi = B * NI * CC * HW;
    const int n_mpi = B * NI * HW;
    float* __restrict__ out_gpi  = out;
    float* __restrict__ out_mpi  = out + n_gpi;
    float* __restrict__ out_gmid = out + n_gpi + n_mpi;
    float* __restrict__ out_mmid = out_gmid + B * CC * HW;
    float* __restrict__ out_ibas = out_mmid + B * HW;

    // --- zero stores for inactive instances (streaming) ---
    const int ninact = s_ninact;
    for (int k = 0; k < ninact; ++k) {
        const int ni = s_inact_ni[k];
        const int bgi = (b * NI + ni) * CC * HW + pix;
        const int bmi = (b * NI + ni) * HW + pix;
        stcs(out_gpi + bgi,          0.0f);
        stcs(out_gpi + bgi + HW,     0.0f);
        stcs(out_gpi + bgi + 2 * HW, 0.0f);
        stcs(out_mpi + bmi,          0.0f);
    }

    float gacc0 = 0.0f, gacc1 = 0.0f, gacc2 = 0.0f, macc = 0.0f;

    // --- hot loop: active instances only ---
    const int nact = s_nact;
    for (int j = 0; j < nact; ++j) {
        const int   ni   = s_act_ni[j];
        const float coef = s_act_coef[j];
        const int base_g = (b * NI + ni) * CC * HW;
        const int base_m = (b * NI + ni) * HW;

        const float ix = fmaf(s_act_t0[j], xf, s_act_bx[j]);
        const float iy = fmaf(s_act_t3[j], xf, s_act_by[j]);

        const int x0 = __float2int_rd(ix);
        const int y0 = __float2int_rd(iy);
        const float wx1 = ix - (float)x0;
        const float wy1 = iy - (float)y0;
        const float wx0 = 1.0f - wx1;
        const float wy0 = 1.0f - wy1;
        const float wy0c = wy0 * coef;
        const float wy1c = wy1 * coef;

        int i00, i10, i01, i11;
        float w00, w10, w01, w11;

        const bool inter = (x0 >= 0) & (x0 <= WW - 2) & (y0 >= 0) & (y0 <= HH - 2);
        if (__all_sync(0xFFFFFFFFu, inter)) {
            // fast path: no clamps, no validity selects, cheap index arithmetic
            i00 = y0 * WW + x0;
            i10 = i00 + 1;
            i01 = i00 + WW;
            i11 = i00 + WW + 1;
            w00 = wx0 * wy0c;
            w10 = wx1 * wy0c;
            w01 = wx0 * wy1c;
            w11 = wx1 * wy1c;
        } else {
            const int x1 = x0 + 1, y1 = y0 + 1;
            const bool vx0 = (x0 >= 0) & (x0 < WW);
            const bool vx1 = (x1 >= 0) & (x1 < WW);
            const bool vy0 = (y0 >= 0) & (y0 < HH);
            const bool vy1 = (y1 >= 0) & (y1 < HH);
            const int x0c = min(max(x0, 0), WW - 1);
            const int x1c = min(max(x1, 0), WW - 1);
            const int y0c = min(max(y0, 0), HH - 1);
            const int y1c = min(max(y1, 0), HH - 1);
            w00 = wx0 * wy0c * ((vx0 & vy0) ? 1.0f : 0.0f);
            w10 = wx1 * wy0c * ((vx1 & vy0) ? 1.0f : 0.0f);
            w01 = wx0 * wy1c * ((vx0 & vy1) ? 1.0f : 0.0f);
            w11 = wx1 * wy1c * ((vx1 & vy1) ? 1.0f : 0.0f);
            i00 = y0c * WW + x0c;
            i10 = y0c * WW + x1c;
            i01 = y1c * WW + x0c;
            i11 = y1c * WW + x1c;
        }

        const float* __restrict__ s0 = g0 + base_g;
        const float* __restrict__ s1 = s0 + HW;
        const float* __restrict__ s2 = s1 + HW;
        const float* __restrict__ sm = m0 + base_m;

        // 16 independent loads in flight
        const float a00 = __ldg(s0 + i00), a10 = __ldg(s0 + i10),
                    a01 = __ldg(s0 + i01), a11 = __ldg(s0 + i11);
        const float b00 = __ldg(s1 + i00), b10 = __ldg(s1 + i10),
                    b01 = __ldg(s1 + i01), b11 = __ldg(s1 + i11);
        const float c00 = __ldg(s2 + i00), c10 = __ldg(s2 + i10),
                    c01 = __ldg(s2 + i01), c11 = __ldg(s2 + i11);
        const float d00 = __ldg(sm + i00), d10 = __ldg(sm + i10),
                    d01 = __ldg(sm + i01), d11 = __ldg(sm + i11);

        const float g0v = w00 * a00 + w10 * a10 + w01 * a01 + w11 * a11;
        const float g1v = w00 * b00 + w10 * b10 + w01 * b01 + w11 * b11;
        const float g2v = w00 * c00 + w10 * c10 + w01 * c01 + w11 * c11;
        const float mv  = w00 * d00 + w10 * d10 + w01 * d01 + w11 * d11;

        stcs(out_gpi + base_g + pix,          g0v);
        stcs(out_gpi + base_g + HW + pix,     g1v);
        stcs(out_gpi + base_g + 2 * HW + pix, g2v);
        stcs(out_mpi + base_m + pix,          mv);

        gacc0 += g0v; gacc1 += g1v; gacc2 += g2v; macc += mv;
    }

    // --- reductions + composite (streaming stores) ---
    const int bg = b * CC * HW + pix;
    stcs(out_gmid + bg,          gacc0);
    stcs(out_gmid + bg + HW,     gacc1);
    stcs(out_gmid + bg + 2 * HW, gacc2);
    stcs(out_mmid + b * HW + pix, fminf(fmaxf(macc, 0.0f), 1.0f));
    stcs(out_ibas + bg,          __ldg(i_bg + bg)          + gacc0);
    stcs(out_ibas + bg + HW,     __ldg(i_bg + bg + HW)     + gacc1);
    stcs(out_ibas + bg + 2 * HW, __ldg(i_bg + bg + 2 * HW) + gacc2);
}

extern "C" void kernel_launch(void* const* d_in, const int* in_sizes, int n_in,
                              void* d_out, int out_size) {
    const float* g0          = (const float*)d_in[0];
    const float* m0          = (const float*)d_in[1];
    const float* mode_logits = (const float*)d_in[2];
    const float* tp          = (const float*)d_in[3];
    const float* alpha       = (const float*)d_in[4];
    const float* inst_valid  = (const float*)d_in[5];
    const float* i_bg        = (const float*)d_in[6];
    float* out = (float*)d_out;

    const int B = in_sizes[0] / (NI * CC * HW);

    dim3 grid(B * HH * 2);   // (b*256 + y)*2 + xtile
    dim3 block(128);
    warp_renderer_kernel<<<grid, block>>>(g0, m0, mode_logits, tp, alpha,
                                          inst_valid, i_bg, out, B);
}